// round 2
// baseline (speedup 1.0000x reference)
#include <cuda_runtime.h>

#define NSHAPES 32
#define TPB 256
#define PPT 8           // points per thread (4 float4 loads)

typedef unsigned long long u64;

__device__ __forceinline__ u64 ffma2(u64 a, u64 b, u64 c) {
    u64 d;
    asm("fma.rn.f32x2 %0, %1, %2, %3;" : "=l"(d) : "l"(a), "l"(b), "l"(c));
    return d;
}
__device__ __forceinline__ u64 pack2(float lo, float hi) {
    u64 d;
    asm("mov.b64 %0, {%1, %2};" : "=l"(d) : "f"(lo), "f"(hi));
    return d;
}
__device__ __forceinline__ void unpack2(u64 v, float& lo, float& hi) {
    asm("mov.b64 {%0, %1}, %2;" : "=f"(lo), "=f"(hi) : "l"(v));
}
__device__ __forceinline__ float sqrt_approx(float x) {
    float r;
    asm("sqrt.approx.f32 %0, %1;" : "=f"(r) : "f"(x));
    return r;
}

__global__ __launch_bounds__(TPB)
void multi_rect_sdf_kernel(const float* __restrict__ query,
                           const float* __restrict__ trans,
                           const float* __restrict__ rads,
                           const float* __restrict__ angles,
                           float* __restrict__ out,
                           int npts)
{
    // Per-shape constants, duplicated-packed so LDS.64 yields ready FFMA2 operands.
    // Layout per shape: {c,c},{s,s},{-s,-s},{-tx,-tx},{-ty,-ty},{-rx,-ry}
    __shared__ float2 sh[NSHAPES * 6];

    const int t = threadIdx.x;
    if (t < NSHAPES) {
        float ang = angles[t];
        float c = cosf(ang), s = sinf(ang);
        float tx = trans[2 * t], ty = trans[2 * t + 1];
        float rx = rads[2 * t], ry = rads[2 * t + 1];
        sh[t * 6 + 0] = make_float2(c, c);
        sh[t * 6 + 1] = make_float2(s, s);
        sh[t * 6 + 2] = make_float2(-s, -s);
        sh[t * 6 + 3] = make_float2(-tx, -tx);
        sh[t * 6 + 4] = make_float2(-ty, -ty);
        sh[t * 6 + 5] = make_float2(-rx, -ry);
    }
    __syncthreads();

    // Block tile: TPB*PPT consecutive points. Thread t handles point pairs
    // (base + k*TPB*2 + t*2) for k=0..3 -> fully coalesced float4 loads.
    const int base = blockIdx.x * (TPB * PPT);
    const bool full = (base + TPB * PPT) <= npts;   // every block at N=2M

    u64 QX[PPT / 2], QY[PPT / 2];
#pragma unroll
    for (int k = 0; k < PPT / 2; k++) {
        int p = base + k * (TPB * 2) + t * 2;
        if (full || p + 1 < npts) {
            float4 q = *reinterpret_cast<const float4*>(query + (size_t)p * 2);
            QX[k] = pack2(q.x, q.z);
            QY[k] = pack2(q.y, q.w);
        } else {
            QX[k] = pack2(0.f, 0.f);
            QY[k] = pack2(0.f, 0.f);
        }
    }

    float minSq[PPT], minIn[PPT];
#pragma unroll
    for (int i = 0; i < PPT; i++) { minSq[i] = 3.0e38f; minIn[i] = 3.0e38f; }

#pragma unroll 4
    for (int j = 0; j < NSHAPES; j++) {
        const u64 C2   = *reinterpret_cast<const u64*>(&sh[j * 6 + 0]);
        const u64 S2   = *reinterpret_cast<const u64*>(&sh[j * 6 + 1]);
        const u64 NS2  = *reinterpret_cast<const u64*>(&sh[j * 6 + 2]);
        const u64 NTX2 = *reinterpret_cast<const u64*>(&sh[j * 6 + 3]);
        const u64 NTY2 = *reinterpret_cast<const u64*>(&sh[j * 6 + 4]);
        const float2 nr = sh[j * 6 + 5];   // (-rx, -ry)

#pragma unroll
        for (int k = 0; k < PPT / 2; k++) {
            // Rotated+translated coords for 2 points at once (packed f32x2).
            u64 A = ffma2(C2, QX[k], ffma2(NS2, QY[k], NTX2));
            u64 B = ffma2(S2, QX[k], ffma2(C2, QY[k], NTY2));
            float a0, a1, b0, b1;
            unpack2(A, a0, a1);
            unpack2(B, b0, b1);

            {   // point 2k
                float dx = fabsf(a0) + nr.x;          // FADD |a| - rx  (fma pipe)
                float dy = fabsf(b0) + nr.y;
                float mx = fmaxf(dx, 0.f);            // FMNMX (alu pipe)
                float my = fmaxf(dy, 0.f);
                float sq = fmaf(my, my, mx * mx);
                minSq[2 * k]     = fminf(minSq[2 * k], sq);
                minIn[2 * k]     = fminf(minIn[2 * k], fmaxf(dx, dy));
            }
            {   // point 2k+1
                float dx = fabsf(a1) + nr.x;
                float dy = fabsf(b1) + nr.y;
                float mx = fmaxf(dx, 0.f);
                float my = fmaxf(dy, 0.f);
                float sq = fmaf(my, my, mx * mx);
                minSq[2 * k + 1] = fminf(minSq[2 * k + 1], sq);
                minIn[2 * k + 1] = fminf(minIn[2 * k + 1], fmaxf(dx, dy));
            }
        }
    }

#pragma unroll
    for (int k = 0; k < PPT / 2; k++) {
        int p = base + k * (TPB * 2) + t * 2;
        if (full || p + 1 < npts) {
            float2 r;
            float s0 = sqrt_approx(minSq[2 * k]);
            float s1 = sqrt_approx(minSq[2 * k + 1]);
            r.x = (minIn[2 * k]     < 0.f) ? minIn[2 * k]     : s0;
            r.y = (minIn[2 * k + 1] < 0.f) ? minIn[2 * k + 1] : s1;
            *reinterpret_cast<float2*>(out + p) = r;
        } else if (p < npts) {
            float s0 = sqrt_approx(minSq[2 * k]);
            out[p] = (minIn[2 * k] < 0.f) ? minIn[2 * k] : s0;
        }
    }
}

extern "C" void kernel_launch(void* const* d_in, const int* in_sizes, int n_in,
                              void* d_out, int out_size)
{
    const float* query  = (const float*)d_in[0];   // (N, 2)
    const float* trans  = (const float*)d_in[1];   // (32, 2)
    const float* rads   = (const float*)d_in[2];   // (32, 2)
    const float* angles = (const float*)d_in[3];   // (32,)
    float* out = (float*)d_out;

    int npts = in_sizes[0] / 2;
    int pts_per_block = TPB * PPT;
    int nblocks = (npts + pts_per_block - 1) / pts_per_block;

    multi_rect_sdf_kernel<<<nblocks, TPB>>>(query, trans, rads, angles, out, npts);
}